// round 2
// baseline (speedup 1.0000x reference)
#include <cuda_runtime.h>

#define BB 16
#define QL 16
#define DD 256
#define NH 4
#define HD 64
#define PLEN 512
#define GLEN 16384
#define MAXS 16

// ------------------------- scratch (device globals) -------------------------
__device__ float g_hk_g[(size_t)BB * GLEN * DD];   // 256 MB
__device__ float g_hv_g[(size_t)BB * GLEN * DD];   // 256 MB
__device__ float g_hk_p[BB * PLEN * DD];
__device__ float g_hv_p[BB * PLEN * DD];
__device__ float g_mem[2][BB * QL * DD];
__device__ float g_hq[BB * QL * DD];
__device__ float g_vec[BB * QL * DD];
__device__ float g_ao[BB * QL * DD];
__device__ float g_pacc[BB * NH * MAXS * QL * HD];
__device__ float g_pm[BB * NH * MAXS * QL];
__device__ float g_pl[BB * NH * MAXS * QL];

// ------------------------- fast exp on FMA pipe (avoids MUFU) ---------------
__device__ __forceinline__ float fexp(float x) {
    float y = x * 1.4426950408889634f;       // log2(e)
    y = fmaxf(y, -125.0f);
    float n = rintf(y);
    float f = y - n;
    float p = 1.3333558146e-3f;
    p = fmaf(p, f, 9.6181291076e-3f);
    p = fmaf(p, f, 5.5504108664e-2f);
    p = fmaf(p, f, 2.4022650696e-1f);
    p = fmaf(p, f, 6.9314718056e-1f);
    p = fmaf(p, f, 1.0f);
    return __int_as_float(((int)n + 127) << 23) * p;
}

// ------------------------- mean pooling: graph -> mem0 ----------------------
__global__ void __launch_bounds__(256) pool_kernel(const float* __restrict__ graph,
                                                   float* __restrict__ mem0) {
    int bm = blockIdx.x;          // b*16 + m
    int d = threadIdx.x;
    const float* src = graph + (size_t)bm * 1024 * DD + d;
    float s0 = 0.f, s1 = 0.f, s2 = 0.f, s3 = 0.f;
    for (int r = 0; r < 1024; r += 4) {
        s0 += src[(size_t)(r + 0) * DD];
        s1 += src[(size_t)(r + 1) * DD];
        s2 += src[(size_t)(r + 2) * DD];
        s3 += src[(size_t)(r + 3) * DD];
    }
    mem0[(size_t)bm * DD + d] = (s0 + s1 + s2 + s3) * (1.0f / 1024.0f);
}

// ------------------- O[M,256] = X[M,256] @ W[256,256] -----------------------
// grid (2, M/128), 256 threads, 8x8 micro-tile (split fragments)
__global__ void __launch_bounds__(256) gemm_x256(const float* __restrict__ X,
                                                 const float* __restrict__ W,
                                                 float* __restrict__ O) {
    __shared__ float As[16][132];
    __shared__ float Bs[16][132];
    int t = threadIdx.x;
    int tx = t & 15, ty = t >> 4;
    size_t m0 = (size_t)blockIdx.y * 128;
    int n0 = blockIdx.x * 128;
    float acc[8][8];
#pragma unroll
    for (int i = 0; i < 8; i++)
#pragma unroll
        for (int j = 0; j < 8; j++) acc[i][j] = 0.f;

    const float* Xb = X + m0 * 256;
    for (int k0 = 0; k0 < 256; k0 += 16) {
        __syncthreads();
#pragma unroll
        for (int u = 0; u < 2; u++) {
            int f = t + 256 * u;            // 0..511 float4
            int row = f >> 2;
            int kk = (f & 3) << 2;
            float4 v = *(const float4*)(Xb + (size_t)row * 256 + k0 + kk);
            As[kk + 0][row] = v.x;
            As[kk + 1][row] = v.y;
            As[kk + 2][row] = v.z;
            As[kk + 3][row] = v.w;
        }
#pragma unroll
        for (int u = 0; u < 2; u++) {
            int f = t + 256 * u;
            int kk = f >> 5;
            int nn = (f & 31) << 2;
            *(float4*)(&Bs[kk][nn]) =
                *(const float4*)(W + (size_t)(k0 + kk) * 256 + n0 + nn);
        }
        __syncthreads();
#pragma unroll
        for (int k = 0; k < 16; k++) {
            float a[8], b[8];
            *(float4*)(a)     = *(float4*)&As[k][ty * 4];
            *(float4*)(a + 4) = *(float4*)&As[k][64 + ty * 4];
            *(float4*)(b)     = *(float4*)&Bs[k][tx * 4];
            *(float4*)(b + 4) = *(float4*)&Bs[k][64 + tx * 4];
#pragma unroll
            for (int i = 0; i < 8; i++)
#pragma unroll
                for (int j = 0; j < 8; j++) acc[i][j] = fmaf(a[i], b[j], acc[i][j]);
        }
    }
#pragma unroll
    for (int i = 0; i < 8; i++) {
        int r = (i < 4) ? (ty * 4 + i) : (64 + ty * 4 + (i - 4));
        float* orow = O + (m0 + r) * 256 + n0;
        *(float4*)(orow + tx * 4) = make_float4(acc[i][0], acc[i][1], acc[i][2], acc[i][3]);
        *(float4*)(orow + 64 + tx * 4) = make_float4(acc[i][4], acc[i][5], acc[i][6], acc[i][7]);
    }
}

// ------------------------- flash attention (split-K partials) ---------------
// grid (splits, NH, BB), 128 threads
__global__ void __launch_bounds__(128) attn_partial(
    const float* __restrict__ hq, const float* __restrict__ hk,
    const float* __restrict__ hv, const int* __restrict__ mask,
    int klen, int kps) {
    __shared__ float Qs[16][68];
    __shared__ float KV[128 * 64];
    __shared__ float Ps[16][128];
    __shared__ float rowM[16], rowL[16], rowS[16];
    __shared__ int mk[128];

    int t = threadIdx.x;
    int split = blockIdx.x, h = blockIdx.y, b = blockIdx.z;

#pragma unroll
    for (int u = 0; u < 2; u++) {
        int f = t + 128 * u;                // 256 float4
        int r = f >> 4, d4 = (f & 15) << 2;
        *(float4*)&Qs[r][d4] =
            *(const float4*)(hq + (size_t)(b * QL + r) * DD + h * HD + d4);
    }
    if (t < 16) { rowM[t] = -3e38f; rowL[t] = 0.f; rowS[t] = 0.f; }

    int mg = t >> 4, ng = t & 15;           // PV: rows mg*2+{0,1}, cols ng*4..+3
    int sng = t >> 3, smg = t & 7;          // S : rows smg*2+{0,1}, cols sng*8..+7
    float acc[2][4] = {{0.f, 0.f, 0.f, 0.f}, {0.f, 0.f, 0.f, 0.f}};

    int key_base = split * kps;
    for (int kt = 0; kt < kps; kt += 128) {
        int k0 = key_base + kt;
        __syncthreads();                    // KV/Ps free from previous iteration
        // K tile -> KV, swizzled: phys col = d4 ^ (((key>>3)&15)<<2)
#pragma unroll
        for (int u = 0; u < 16; u++) {
            int f = t + 128 * u;            // 2048 float4
            int key = f >> 4, d4 = (f & 15) << 2;
            int c4 = ((key >> 3) & 15) << 2;
            *(float4*)&KV[key * 64 + (d4 ^ c4)] =
                *(const float4*)(hk + ((size_t)b * klen + k0 + key) * DD + h * HD + d4);
        }
        mk[t] = mask[(size_t)b * klen + k0 + t];
        __syncthreads();
        // ---- scores S = Q K^T * scale, masked ----
        {
            float s0[8] = {0, 0, 0, 0, 0, 0, 0, 0};
            float s1[8] = {0, 0, 0, 0, 0, 0, 0, 0};
            int r0 = smg * 2;
#pragma unroll
            for (int kd = 0; kd < 64; kd += 4) {
                float4 q0 = *(float4*)&Qs[r0][kd];
                float4 q1 = *(float4*)&Qs[r0 + 1][kd];
#pragma unroll
                for (int j = 0; j < 8; j++) {
                    int key = sng * 8 + j;
                    int c4 = ((key >> 3) & 15) << 2;
                    float4 kv = *(float4*)&KV[key * 64 + (kd ^ c4)];
                    s0[j] = fmaf(q0.x, kv.x, s0[j]); s0[j] = fmaf(q0.y, kv.y, s0[j]);
                    s0[j] = fmaf(q0.z, kv.z, s0[j]); s0[j] = fmaf(q0.w, kv.w, s0[j]);
                    s1[j] = fmaf(q1.x, kv.x, s1[j]); s1[j] = fmaf(q1.y, kv.y, s1[j]);
                    s1[j] = fmaf(q1.z, kv.z, s1[j]); s1[j] = fmaf(q1.w, kv.w, s1[j]);
                }
            }
#pragma unroll
            for (int j = 0; j < 8; j++) {
                int key = sng * 8 + j;
                float v0 = s0[j] * 0.125f, v1 = s1[j] * 0.125f;
                if (mk[key] == 0) { v0 = -1e30f; v1 = -1e30f; }
                Ps[r0][key] = v0;
                Ps[r0 + 1][key] = v1;
            }
        }
        __syncthreads();
        // ---- online softmax stats for this tile ----
        {
            int row = t >> 3, sub = t & 7;
            float lmax = -3e38f;
#pragma unroll
            for (int i = 0; i < 16; i++) lmax = fmaxf(lmax, Ps[row][sub * 16 + i]);
#pragma unroll
            for (int o = 4; o; o >>= 1) lmax = fmaxf(lmax, __shfl_xor_sync(~0u, lmax, o));
            float oldm = rowM[row];
            float newm = fmaxf(oldm, lmax);
            float lsum = 0.f;
#pragma unroll
            for (int i = 0; i < 16; i++) {
                int c = sub * 16 + i;
                float p = fexp(Ps[row][c] - newm);
                Ps[row][c] = p;
                lsum += p;
            }
#pragma unroll
            for (int o = 4; o; o >>= 1) lsum += __shfl_xor_sync(~0u, lsum, o);
            if (sub == 0) {
                float sc = fexp(oldm - newm);
                rowS[row] = sc;
                rowL[row] = rowL[row] * sc + lsum;
                rowM[row] = newm;
            }
        }
        // ---- V tile -> KV (K no longer needed) ----
#pragma unroll
        for (int u = 0; u < 16; u++) {
            int f = t + 128 * u;
            int key = f >> 4, d4 = (f & 15) << 2;
            int c4 = ((key >> 3) & 15) << 2;
            *(float4*)&KV[key * 64 + (d4 ^ c4)] =
                *(const float4*)(hv + ((size_t)b * klen + k0 + key) * DD + h * HD + d4);
        }
        __syncthreads();
        // ---- rescale + acc += P @ V ----
        {
            float sc0 = rowS[mg * 2], sc1 = rowS[mg * 2 + 1];
#pragma unroll
            for (int j = 0; j < 4; j++) { acc[0][j] *= sc0; acc[1][j] *= sc1; }
            int r0 = mg * 2, c0 = ng * 4;
            for (int kk = 0; kk < 128; kk += 4) {
                float4 p0 = *(float4*)&Ps[r0][kk];
                float4 p1 = *(float4*)&Ps[r0 + 1][kk];
                float pa0[4] = {p0.x, p0.y, p0.z, p0.w};
                float pa1[4] = {p1.x, p1.y, p1.z, p1.w};
#pragma unroll
                for (int jj = 0; jj < 4; jj++) {
                    int key = kk + jj;
                    int c4 = ((key >> 3) & 15) << 2;
                    float4 vv = *(float4*)&KV[key * 64 + (c0 ^ c4)];
                    acc[0][0] = fmaf(pa0[jj], vv.x, acc[0][0]);
                    acc[0][1] = fmaf(pa0[jj], vv.y, acc[0][1]);
                    acc[0][2] = fmaf(pa0[jj], vv.z, acc[0][2]);
                    acc[0][3] = fmaf(pa0[jj], vv.w, acc[0][3]);
                    acc[1][0] = fmaf(pa1[jj], vv.x, acc[1][0]);
                    acc[1][1] = fmaf(pa1[jj], vv.y, acc[1][1]);
                    acc[1][2] = fmaf(pa1[jj], vv.z, acc[1][2]);
                    acc[1][3] = fmaf(pa1[jj], vv.w, acc[1][3]);
                }
            }
        }
    }
    __syncthreads();
    size_t pbase = ((size_t)(b * NH + h) * MAXS + split) * QL;
    float* pa = g_pacc + pbase * HD;
#pragma unroll
    for (int i = 0; i < 2; i++) {
        int r = mg * 2 + i;
        *(float4*)(pa + (size_t)r * HD + ng * 4) =
            make_float4(acc[i][0], acc[i][1], acc[i][2], acc[i][3]);
    }
    if (t < 16) { g_pm[pbase + t] = rowM[t]; g_pl[pbase + t] = rowL[t]; }
}

// ------------------------- merge split-K partials ---------------------------
__global__ void __launch_bounds__(256) attn_merge(float* __restrict__ vec, int nsplit) {
    __shared__ float w[MAXS][16];
    __shared__ float invL[16];
    int t = threadIdx.x;
    int h = blockIdx.x, b = blockIdx.y;
    size_t base = (size_t)(b * NH + h) * MAXS * QL;
    if (t < 16) {
        float M = -3e38f;
        for (int s = 0; s < nsplit; s++) M = fmaxf(M, g_pm[base + s * QL + t]);
        float L = 0.f;
        for (int s = 0; s < nsplit; s++) {
            float ww = fexp(g_pm[base + s * QL + t] - M);
            w[s][t] = ww;
            L += g_pl[base + s * QL + t] * ww;
        }
        invL[t] = 1.f / L;
    }
    __syncthreads();
    int r = t >> 4, c4 = (t & 15) << 2;
    float ox = 0.f, oy = 0.f, oz = 0.f, ow = 0.f;
    for (int s = 0; s < nsplit; s++) {
        float ww = w[s][r];
        float4 a = *(const float4*)(g_pacc + (base + s * QL + r) * HD + c4);
        ox = fmaf(a.x, ww, ox); oy = fmaf(a.y, ww, oy);
        oz = fmaf(a.z, ww, oz); ow = fmaf(a.w, ww, ow);
    }
    float il = invL[r];
    *(float4*)(vec + (size_t)(b * QL + r) * DD + h * HD + c4) =
        make_float4(ox * il, oy * il, oz * il, ow * il);
}

// ------------------------- gate + residual ----------------------------------
// grid 256 (row), 256 threads (col)
__global__ void __launch_bounds__(256) gate_kernel(
    const float* __restrict__ mem, const float* __restrict__ ao,
    const float* __restrict__ Wg, const float* __restrict__ bg,
    float* __restrict__ out) {
    __shared__ float xs[512];
    int row = blockIdx.x;
    int c = threadIdx.x;
    xs[c] = mem[(size_t)row * DD + c];
    xs[256 + c] = ao[(size_t)row * DD + c];
    __syncthreads();
    float s0 = 0.f, s1 = 0.f, s2 = 0.f, s3 = 0.f;
#pragma unroll 4
    for (int k = 0; k < 512; k += 4) {
        float4 x = *(float4*)&xs[k];
        s0 = fmaf(x.x, Wg[(size_t)(k + 0) * DD + c], s0);
        s1 = fmaf(x.y, Wg[(size_t)(k + 1) * DD + c], s1);
        s2 = fmaf(x.z, Wg[(size_t)(k + 2) * DD + c], s2);
        s3 = fmaf(x.w, Wg[(size_t)(k + 3) * DD + c], s3);
    }
    float sum = (s0 + s1) + (s2 + s3) + bg[c];
    float gate = 1.f / (1.f + fexp(-sum));
    out[(size_t)row * DD + c] = gate * xs[c] + (1.f - gate) * xs[256 + c];
}

// ------------------------- launch -------------------------------------------
extern "C" void kernel_launch(void* const* d_in, const int* in_sizes, int n_in,
                              void* d_out, int out_size) {
    const float* pattern = (const float*)d_in[0];
    const float* graph = (const float*)d_in[1];
    const int* pmask = (const int*)d_in[2];
    const int* gmask = (const int*)d_in[3];
    const float* pW[6];
    const float* gW[6];
    for (int i = 0; i < 6; i++) pW[i] = (const float*)d_in[4 + i];
    for (int i = 0; i < 6; i++) gW[i] = (const float*)d_in[10 + i];
    float* out = (float*)d_out;

    float *hkg, *hvg, *hkp, *hvp, *memb, *hq, *vec, *ao;
    cudaGetSymbolAddress((void**)&hkg, g_hk_g);
    cudaGetSymbolAddress((void**)&hvg, g_hv_g);
    cudaGetSymbolAddress((void**)&hkp, g_hk_p);
    cudaGetSymbolAddress((void**)&hvp, g_hv_p);
    cudaGetSymbolAddress((void**)&memb, g_mem);
    cudaGetSymbolAddress((void**)&hq, g_hq);
    cudaGetSymbolAddress((void**)&vec, g_vec);
    cudaGetSymbolAddress((void**)&ao, g_ao);
    float* mem0 = memb;
    float* mem1 = memb + BB * QL * DD;

    pool_kernel<<<256, 256>>>(graph, mem0);
    gemm_x256<<<dim3(2, BB * PLEN / 128), 256>>>(pattern, pW[1], hkp);
    gemm_x256<<<dim3(2, BB * PLEN / 128), 256>>>(pattern, pW[2], hvp);
    gemm_x256<<<dim3(2, BB * GLEN / 128), 256>>>(graph, gW[1], hkg);
    gemm_x256<<<dim3(2, BB * GLEN / 128), 256>>>(graph, gW[2], hvg);

    float* cur = mem0;
    float* other = mem1;
    for (int it = 0; it < 3; it++) {
        for (int ph = 0; ph < 2; ph++) {
            const float* const* W = ph ? gW : pW;
            const float* hk = ph ? hkg : hkp;
            const float* hv = ph ? hvg : hvp;
            const int* mask = ph ? gmask : pmask;
            int klen = ph ? GLEN : PLEN;
            int splits = ph ? 16 : 4;
            int kps = klen / splits;

            gemm_x256<<<dim3(2, 2), 256>>>(cur, W[0], hq);
            attn_partial<<<dim3(splits, NH, BB), 128>>>(hq, hk, hv, mask, klen, kps);
            attn_merge<<<dim3(NH, BB), 256>>>(vec, splits);
            gemm_x256<<<dim3(2, 2), 256>>>(vec, W[3], ao);

            bool last = (it == 2 && ph == 1);
            float* dst = last ? out : other;
            gate_kernel<<<256, 256>>>(cur, ao, W[4], W[5], dst);
            other = cur;
            cur = dst;
        }
    }
}

// round 4
// speedup vs baseline: 1.2175x; 1.2175x over previous
#include <cuda_runtime.h>
#include <cuda_bf16.h>
#include <cstdint>

#define BB 16
#define QL 16
#define DD 256
#define NH 4
#define HD 64
#define PLEN 512
#define GLEN 16384
#define MAXS 32
#define GM (BB * GLEN)      // 262144
#define PM (BB * PLEN)      // 8192

// ------------------------- scratch (device globals) -------------------------
__device__ float g_hk_g[(size_t)GM * DD];            // 256 MB
__device__ float g_hv_g[(size_t)GM * DD];            // 256 MB
__device__ float g_hk_p[PM * DD];
__device__ float g_hv_p[PM * DD];
__device__ __nv_bfloat16 g_xh_g[(size_t)GM * DD];    // 128 MB
__device__ __nv_bfloat16 g_xl_g[(size_t)GM * DD];    // 128 MB
__device__ __nv_bfloat16 g_xh_p[PM * DD];
__device__ __nv_bfloat16 g_xl_p[PM * DD];
__device__ __nv_bfloat16 g_wt[8][DD * DD];           // pKh,pKl,pVh,pVl,gKh,gKl,gVh,gVl
__device__ float g_mem[2][BB * QL * DD];
__device__ float g_hq[BB * QL * DD];
__device__ float g_vec[BB * QL * DD];
__device__ float g_ao[BB * QL * DD];
__device__ float g_pacc[BB * NH * MAXS * QL * HD];
__device__ float g_pm[BB * NH * MAXS * QL];
__device__ float g_pl[BB * NH * MAXS * QL];

// ------------------------- fast exp on FMA pipe -----------------------------
__device__ __forceinline__ float fexp(float x) {
    float y = x * 1.4426950408889634f;
    y = fmaxf(y, -125.0f);
    float n = rintf(y);
    float f = y - n;
    float p = 1.3333558146e-3f;
    p = fmaf(p, f, 9.6181291076e-3f);
    p = fmaf(p, f, 5.5504108664e-2f);
    p = fmaf(p, f, 2.4022650696e-1f);
    p = fmaf(p, f, 6.9314718056e-1f);
    p = fmaf(p, f, 1.0f);
    return __int_as_float(((int)n + 127) << 23) * p;
}

// ------------------------- mma helpers --------------------------------------
__device__ __forceinline__ uint32_t smem_u32(const void* p) {
    uint32_t a;
    asm("{ .reg .u64 t; cvta.to.shared.u64 t, %1; cvt.u32.u64 %0, t; }" : "=r"(a) : "l"(p));
    return a;
}
__device__ __forceinline__ void ldm_x4(uint32_t* r, uint32_t addr) {
    asm volatile("ldmatrix.sync.aligned.m8n8.x4.shared.b16 {%0,%1,%2,%3}, [%4];"
                 : "=r"(r[0]), "=r"(r[1]), "=r"(r[2]), "=r"(r[3]) : "r"(addr));
}
__device__ __forceinline__ void mma_bf16(float* c, const uint32_t* a, const uint32_t* b) {
    asm volatile(
        "mma.sync.aligned.m16n8k16.row.col.f32.bf16.bf16.f32 "
        "{%0,%1,%2,%3}, {%4,%5,%6,%7}, {%8,%9}, {%0,%1,%2,%3};"
        : "+f"(c[0]), "+f"(c[1]), "+f"(c[2]), "+f"(c[3])
        : "r"(a[0]), "r"(a[1]), "r"(a[2]), "r"(a[3]), "r"(b[0]), "r"(b[1]));
}

// ------------------------- split fp32 -> (bf16 hi, bf16 lo) -----------------
__global__ void __launch_bounds__(256) split_x(const float* __restrict__ X,
                                               __nv_bfloat16* __restrict__ Xh,
                                               __nv_bfloat16* __restrict__ Xl, int n4) {
    int i = blockIdx.x * 256 + threadIdx.x;
    if (i >= n4) return;
    float4 v = ((const float4*)X)[i];
    float f[4] = {v.x, v.y, v.z, v.w};
    __nv_bfloat16 h[4], l[4];
#pragma unroll
    for (int j = 0; j < 4; j++) {
        h[j] = __float2bfloat16(f[j]);
        l[j] = __float2bfloat16(f[j] - __bfloat162float(h[j]));
    }
    ((__nv_bfloat162*)Xh)[2 * (size_t)i] = __nv_bfloat162(h[0], h[1]);
    ((__nv_bfloat162*)Xh)[2 * (size_t)i + 1] = __nv_bfloat162(h[2], h[3]);
    ((__nv_bfloat162*)Xl)[2 * (size_t)i] = __nv_bfloat162(l[0], l[1]);
    ((__nv_bfloat162*)Xl)[2 * (size_t)i + 1] = __nv_bfloat162(l[2], l[3]);
}

// W[256,256] -> transposed split: T[n][k]
__global__ void __launch_bounds__(256) split_wt(const float* __restrict__ W,
                                                __nv_bfloat16* __restrict__ Th,
                                                __nv_bfloat16* __restrict__ Tl) {
    int n = blockIdx.x, k = threadIdx.x;
    float v = W[(size_t)k * DD + n];
    __nv_bfloat16 h = __float2bfloat16(v);
    Th[(size_t)n * DD + k] = h;
    Tl[(size_t)n * DD + k] = __float2bfloat16(v - __bfloat162float(h));
}

// ---------------- mma.sync GEMM: O[M,256] = X[M,256] @ Wt^T -----------------
// X as bf16 hi/lo, Wt as [n][k] bf16 hi/lo. grid (2, M/128), 256 threads.
// Block tile 128x128, BK=32, warp tile 32x64 (4x2 warps), 3-pass hi/lo.
#define APAD 40   // padded k-stride in bf16 (80 bytes -> conflict-free ldmatrix)

__global__ void __launch_bounds__(256) gemm_mma(
    const __nv_bfloat16* __restrict__ Xh, const __nv_bfloat16* __restrict__ Xl,
    const __nv_bfloat16* __restrict__ Wh, const __nv_bfloat16* __restrict__ Wl,
    float* __restrict__ O) {
    __shared__ __nv_bfloat16 Ah[128 * APAD];
    __shared__ __nv_bfloat16 Al[128 * APAD];
    __shared__ __nv_bfloat16 Bh[128 * APAD];
    __shared__ __nv_bfloat16 Bl[128 * APAD];

    int t = threadIdx.x;
    int wid = t >> 5, lane = t & 31;
    int wm = (wid & 3) * 32;       // warp row offset
    int wn = (wid >> 2) * 64;      // warp col offset
    size_t m0 = (size_t)blockIdx.y * 128;
    int n0 = blockIdx.x * 128;

    uint32_t sAh = smem_u32(Ah), sAl = smem_u32(Al);
    uint32_t sBh = smem_u32(Bh), sBl = smem_u32(Bl);

    float acc[2][8][4];
#pragma unroll
    for (int i = 0; i < 2; i++)
#pragma unroll
        for (int j = 0; j < 8; j++)
#pragma unroll
            for (int e = 0; e < 4; e++) acc[i][j][e] = 0.f;

    for (int k0 = 0; k0 < 256; k0 += 32) {
        __syncthreads();
        // load A/B tiles (128 rows x 32 bf16, 4x16B chunks per row)
#pragma unroll
        for (int u = 0; u < 2; u++) {
            int f = t + 256 * u;          // 0..511
            int row = f >> 2, c = f & 3;
            uint32_t so = (uint32_t)(row * APAD * 2 + c * 16);
            const uint4* ga = (const uint4*)(Xh + (m0 + row) * DD + k0) + c;
            *(uint4*)((char*)Ah + so) = *ga;
            ga = (const uint4*)(Xl + (m0 + row) * DD + k0) + c;
            *(uint4*)((char*)Al + so) = *ga;
            ga = (const uint4*)(Wh + (size_t)(n0 + row) * DD + k0) + c;
            *(uint4*)((char*)Bh + so) = *ga;
            ga = (const uint4*)(Wl + (size_t)(n0 + row) * DD + k0) + c;
            *(uint4*)((char*)Bl + so) = *ga;
        }
        __syncthreads();

#pragma unroll
        for (int s = 0; s < 2; s++) {
            int kk = s * 16;
            uint32_t aH[2][4], aL[2][4], bH[8][2], bL[8][2];
            // A fragments (2 m16 tiles)
#pragma unroll
            for (int i = 0; i < 2; i++) {
                int q = lane >> 3, r8 = lane & 7;
                int row = wm + i * 16 + (q & 1) * 8 + r8;
                int col = kk + (q >> 1) * 8;
                uint32_t off = (uint32_t)(row * APAD + col) * 2;
                ldm_x4(aH[i], sAh + off);
                ldm_x4(aL[i], sAl + off);
            }
            // B fragments (8 n8 tiles, 2 tiles per ldmatrix.x4)
#pragma unroll
            for (int p = 0; p < 4; p++) {
                int q = lane >> 3, r8 = lane & 7;
                int n = wn + p * 16 + (q >> 1) * 8 + r8;
                int col = kk + (q & 1) * 8;
                uint32_t off = (uint32_t)(n * APAD + col) * 2;
                uint32_t rh[4], rl[4];
                ldm_x4(rh, sBh + off);
                ldm_x4(rl, sBl + off);
                bH[2 * p][0] = rh[0]; bH[2 * p][1] = rh[1];
                bH[2 * p + 1][0] = rh[2]; bH[2 * p + 1][1] = rh[3];
                bL[2 * p][0] = rl[0]; bL[2 * p][1] = rl[1];
                bL[2 * p + 1][0] = rl[2]; bL[2 * p + 1][1] = rl[3];
            }
            // 3-pass hi/lo MMA
#pragma unroll
            for (int i = 0; i < 2; i++)
#pragma unroll
                for (int j = 0; j < 8; j++) {
                    mma_bf16(acc[i][j], aH[i], bH[j]);
                    mma_bf16(acc[i][j], aH[i], bL[j]);
                    mma_bf16(acc[i][j], aL[i], bH[j]);
                }
        }
    }
    // epilogue
#pragma unroll
    for (int i = 0; i < 2; i++) {
        int r0 = wm + i * 16 + (lane >> 2);
#pragma unroll
        for (int j = 0; j < 8; j++) {
            int c = n0 + wn + j * 8 + (lane & 3) * 2;
            *(float2*)(O + (m0 + r0) * DD + c) = make_float2(acc[i][j][0], acc[i][j][1]);
            *(float2*)(O + (m0 + r0 + 8) * DD + c) = make_float2(acc[i][j][2], acc[i][j][3]);
        }
    }
}

// ------------------------- mean pooling: graph -> mem0 ----------------------
__global__ void __launch_bounds__(256) pool_kernel(const float* __restrict__ graph,
                                                   float* __restrict__ mem0) {
    int bm = blockIdx.x;
    int d = threadIdx.x;
    const float* src = graph + (size_t)bm * 1024 * DD + d;
    float s0 = 0.f, s1 = 0.f, s2 = 0.f, s3 = 0.f;
    for (int r = 0; r < 1024; r += 4) {
        s0 += src[(size_t)(r + 0) * DD];
        s1 += src[(size_t)(r + 1) * DD];
        s2 += src[(size_t)(r + 2) * DD];
        s3 += src[(size_t)(r + 3) * DD];
    }
    mem0[(size_t)bm * DD + d] = (s0 + s1 + s2 + s3) * (1.0f / 1024.0f);
}

// ---------------- small GEMM: O[256,256] = X[256,256] @ W[256,256] ----------
__global__ void __launch_bounds__(256) gemm_small(const float* __restrict__ X,
                                                  const float* __restrict__ W,
                                                  float* __restrict__ O) {
    __shared__ float Xs[16][256];
    int t = threadIdx.x;
    int r0 = blockIdx.y * 16, n0 = blockIdx.x * 64;
#pragma unroll
    for (int u = 0; u < 4; u++) {
        int f = t + 256 * u;
        int row = f >> 6, c4 = (f & 63) << 2;
        *(float4*)&Xs[row][c4] = *(const float4*)(X + (size_t)(r0 + row) * DD + c4);
    }
    __syncthreads();
    int n = n0 + (t & 63), rg = (t >> 6) * 4;
    float a0 = 0.f, a1 = 0.f, a2 = 0.f, a3 = 0.f;
#pragma unroll 8
    for (int k = 0; k < 256; k++) {
        float w = W[(size_t)k * DD + n];
        a0 = fmaf(Xs[rg + 0][k], w, a0);
        a1 = fmaf(Xs[rg + 1][k], w, a1);
        a2 = fmaf(Xs[rg + 2][k], w, a2);
        a3 = fmaf(Xs[rg + 3][k], w, a3);
    }
    O[(size_t)(r0 + rg + 0) * DD + n] = a0;
    O[(size_t)(r0 + rg + 1) * DD + n] = a1;
    O[(size_t)(r0 + rg + 2) * DD + n] = a2;
    O[(size_t)(r0 + rg + 3) * DD + n] = a3;
}

// ------------------------- flash attention (split-K partials) ---------------
__global__ void __launch_bounds__(128) attn_partial(
    const float* __restrict__ hq, const float* __restrict__ hk,
    const float* __restrict__ hv, const int* __restrict__ mask,
    int klen, int kps) {
    __shared__ float Qs[16][68];
    __shared__ float KV[128 * 64];
    __shared__ float Ps[16][128];
    __shared__ float rowM[16], rowL[16], rowS[16];
    __shared__ int mk[128];

    int t = threadIdx.x;
    int split = blockIdx.x, h = blockIdx.y, b = blockIdx.z;

#pragma unroll
    for (int u = 0; u < 2; u++) {
        int f = t + 128 * u;
        int r = f >> 4, d4 = (f & 15) << 2;
        *(float4*)&Qs[r][d4] =
            *(const float4*)(hq + (size_t)(b * QL + r) * DD + h * HD + d4);
    }
    if (t < 16) { rowM[t] = -3e38f; rowL[t] = 0.f; rowS[t] = 0.f; }

    int mg = t >> 4, ng = t & 15;
    int sng = t >> 3, smg = t & 7;
    float acc[2][4] = {{0.f, 0.f, 0.f, 0.f}, {0.f, 0.f, 0.f, 0.f}};

    int key_base = split * kps;
    for (int kt = 0; kt < kps; kt += 128) {
        int k0 = key_base + kt;
        __syncthreads();
#pragma unroll
        for (int u = 0; u < 16; u++) {
            int f = t + 128 * u;
            int key = f >> 4, d4 = (f & 15) << 2;
            int c4 = ((key >> 3) & 15) << 2;
            *(float4*)&KV[key * 64 + (d4 ^ c4)] =
                *(const float4*)(hk + ((size_t)b * klen + k0 + key) * DD + h * HD + d4);
        }
        mk[t] = mask[(size_t)b * klen + k0 + t];
        __syncthreads();
        {
            float s0[8] = {0, 0, 0, 0, 0, 0, 0, 0};
            float s1[8] = {0, 0, 0, 0, 0, 0, 0, 0};
            int r0 = smg * 2;
#pragma unroll
            for (int kd = 0; kd < 64; kd += 4) {
                float4 q0 = *(float4*)&Qs[r0][kd];
                float4 q1 = *(float4*)&Qs[r0 + 1][kd];
#pragma unroll
                for (int j = 0; j < 8; j++) {
                    int key = sng * 8 + j;
                    int c4 = ((key >> 3) & 15) << 2;
                    float4 kv = *(float4*)&KV[key * 64 + (kd ^ c4)];
                    s0[j] = fmaf(q0.x, kv.x, s0[j]); s0[j] = fmaf(q0.y, kv.y, s0[j]);
                    s0[j] = fmaf(q0.z, kv.z, s0[j]); s0[j] = fmaf(q0.w, kv.w, s0[j]);
                    s1[j] = fmaf(q1.x, kv.x, s1[j]); s1[j] = fmaf(q1.y, kv.y, s1[j]);
                    s1[j] = fmaf(q1.z, kv.z, s1[j]); s1[j] = fmaf(q1.w, kv.w, s1[j]);
                }
            }
#pragma unroll
            for (int j = 0; j < 8; j++) {
                int key = sng * 8 + j;
                float v0 = s0[j] * 0.125f, v1 = s1[j] * 0.125f;
                if (mk[key] == 0) { v0 = -1e30f; v1 = -1e30f; }
                Ps[r0][key] = v0;
                Ps[r0 + 1][key] = v1;
            }
        }
        __syncthreads();
        {
            int row = t >> 3, sub = t & 7;
            float lmax = -3e38f;
#pragma unroll
            for (int i = 0; i < 16; i++) lmax = fmaxf(lmax, Ps[row][sub * 16 + i]);
#pragma unroll
            for (int o = 4; o; o >>= 1) lmax = fmaxf(lmax, __shfl_xor_sync(~0u, lmax, o));
            float oldm = rowM[row];
            float newm = fmaxf(oldm, lmax);
            float lsum = 0.f;
#pragma unroll
            for (int i = 0; i < 16; i++) {
                int cc = sub * 16 + i;
                float p = fexp(Ps[row][cc] - newm);
                Ps[row][cc] = p;
                lsum += p;
            }
#pragma unroll
            for (int o = 4; o; o >>= 1) lsum += __shfl_xor_sync(~0u, lsum, o);
            if (sub == 0) {
                float sc = fexp(oldm - newm);
                rowS[row] = sc;
                rowL[row] = rowL[row] * sc + lsum;
                rowM[row] = newm;
            }
        }
#pragma unroll
        for (int u = 0; u < 16; u++) {
            int f = t + 128 * u;
            int key = f >> 4, d4 = (f & 15) << 2;
            int c4 = ((key >> 3) & 15) << 2;
            *(float4*)&KV[key * 64 + (d4 ^ c4)] =
                *(const float4*)(hv + ((size_t)b * klen + k0 + key) * DD + h * HD + d4);
        }
        __syncthreads();
        {
            float sc0 = rowS[mg * 2], sc1 = rowS[mg * 2 + 1];
#pragma unroll
            for (int j = 0; j < 4; j++) { acc[0][j] *= sc0; acc[1][j] *= sc1; }
            int r0 = mg * 2, c0 = ng * 4;
            for (int kk = 0; kk < 128; kk += 4) {
                float4 p0 = *(float4*)&Ps[r0][kk];
                float4 p1 = *(float4*)&Ps[r0 + 1][kk];
                float pa0[4] = {p0.x, p0.y, p0.z, p0.w};
                float pa1[4] = {p1.x, p1.y, p1.z, p1.w};
#pragma unroll
                for (int jj = 0; jj < 4; jj++) {
                    int key = kk + jj;
                    int c4 = ((key >> 3) & 15) << 2;
                    float4 vv = *(float4*)&KV[key * 64 + (c0 ^ c4)];
                    acc[0][0] = fmaf(pa0[jj], vv.x, acc[0][0]);
                    acc[0][1] = fmaf(pa0[jj], vv.y, acc[0][1]);
                    acc[0][2] = fmaf(pa0[jj], vv.z, acc[0][2]);
                    acc[0][3] = fmaf(pa0[jj], vv.w, acc[0][3]);
                    acc[1][0] = fmaf(pa1[jj], vv.x, acc[1][0]);
                    acc[1][1] = fmaf(pa1[jj], vv.y, acc[1][1]);
                    acc[1][2] = fmaf(pa1[jj], vv.z, acc[1][2]);
                    acc[1][3] = fmaf(pa1[jj], vv.w, acc[1][3]);
                }
            }
        }
    }
    __syncthreads();
    size_t pbase = ((size_t)(b * NH + h) * MAXS + split) * QL;
    float* pa = g_pacc + pbase * HD;
#pragma unroll
    for (int i = 0; i < 2; i++) {
        int r = mg * 2 + i;
        *(float4*)(pa + (size_t)r * HD + ng * 4) =
            make_float4(acc[i][0], acc[i][1], acc[i][2], acc[i][3]);
    }
    if (t < 16) { g_pm[pbase + t] = rowM[t]; g_pl[pbase + t] = rowL[t]; }
}

// ------------------------- merge split-K partials ---------------------------
__global__ void __launch_bounds__(256) attn_merge(float* __restrict__ vec, int nsplit) {
    __shared__ float w[MAXS][16];
    __shared__ float invL[16];
    int t = threadIdx.x;
    int h = blockIdx.x, b = blockIdx.y;
    size_t base = (size_t)(b * NH + h) * MAXS * QL;
    if (t < 16) {
        float M = -3e38f;
        for (int s = 0; s < nsplit; s++) M = fmaxf(M, g_pm[base + s * QL + t]);
        float L = 0.f;
        for (int s = 0; s < nsplit; s++) {
            float ww = fexp(g_pm[base + s * QL + t] - M);
            w[s][t] = ww;
            L += g_pl[base + s * QL + t] * ww;
        }
        invL[t] = 1.f / L;
    }
    __syncthreads();
    int r = t >> 4, c4 = (t & 15) << 2;
    float ox = 0.f, oy = 0.f, oz = 0.f, ow = 0.f;
    for (int s = 0; s < nsplit; s++) {
        float ww = w[s][r];
        float4 a = *(const float4*)(g_pacc + (base + s * QL + r) * HD + c4);
        ox = fmaf(a.x, ww, ox); oy = fmaf(a.y, ww, oy);
        oz = fmaf(a.z, ww, oz); ow = fmaf(a.w, ww, ow);
    }
    float il = invL[r];
    *(float4*)(vec + (size_t)(b * QL + r) * DD + h * HD + c4) =
        make_float4(ox * il, oy * il, oz * il, ow * il);
}

// ------------------------- gate + residual ----------------------------------
__global__ void __launch_bounds__(256) gate_kernel(
    const float* __restrict__ mem, const float* __restrict__ ao,
    const float* __restrict__ Wg, const float* __restrict__ bg,
    float* __restrict__ out) {
    __shared__ float xs[512];
    int row = blockIdx.x;
    int c = threadIdx.x;
    xs[c] = mem[(size_t)row * DD + c];
    xs[256 + c] = ao[(size_t)row * DD + c];
    __syncthreads();
    float s0 = 0.f, s1 = 0.f, s2 = 0.f, s3 = 0.f;
#pragma unroll 4
    for (int k = 0; k < 512; k += 4) {
        float4 x = *(float4*)&xs[k];
        s0 = fmaf(x.x, Wg[(size_t)(k + 0) * DD + c], s0);
        s1 = fmaf(x.y, Wg[(size_t)(k + 1) * DD + c], s1);
        s2 = fmaf(x.z, Wg[(size_t)(k + 2) * DD + c], s2);
        s3 = fmaf(x.w, Wg[(size_t)(k + 3) * DD + c], s3);
    }
    float sum = (s0 + s1) + (s2 + s3) + bg[c];
    float gate = 1.f / (1.f + fexp(-sum));
    out[(size_t)row * DD + c] = gate * xs[c] + (1.f - gate) * xs[256 + c];
}

// ------------------------- launch -------------------------------------------
extern "C" void kernel_launch(void* const* d_in, const int* in_sizes, int n_in,
                              void* d_out, int out_size) {
    const float* pattern = (const float*)d_in[0];
    const float* graph = (const float*)d_in[1];
    const int* pmask = (const int*)d_in[2];
    const int* gmask = (const int*)d_in[3];
    const float* pW[6];
    const float* gW[6];
    for (int i = 0; i < 6; i++) pW[i] = (const float*)d_in[4 + i];
    for (int i = 0; i < 6; i++) gW[i] = (const float*)d_in[10 + i];
    float* out = (float*)d_out;

    float *hkg, *hvg, *hkp, *hvp, *memb, *hq, *vec, *ao;
    __nv_bfloat16 *xhg, *xlg, *xhp, *xlp, *wt;
    cudaGetSymbolAddress((void**)&hkg, g_hk_g);
    cudaGetSymbolAddress((void**)&hvg, g_hv_g);
    cudaGetSymbolAddress((void**)&hkp, g_hk_p);
    cudaGetSymbolAddress((void**)&hvp, g_hv_p);
    cudaGetSymbolAddress((void**)&memb, g_mem);
    cudaGetSymbolAddress((void**)&hq, g_hq);
    cudaGetSymbolAddress((void**)&vec, g_vec);
    cudaGetSymbolAddress((void**)&ao, g_ao);
    cudaGetSymbolAddress((void**)&xhg, g_xh_g);
    cudaGetSymbolAddress((void**)&xlg, g_xl_g);
    cudaGetSymbolAddress((void**)&xhp, g_xh_p);
    cudaGetSymbolAddress((void**)&xlp, g_xl_p);
    cudaGetSymbolAddress((void**)&wt, g_wt);
    float* mem0 = memb;
    float* mem1 = memb + BB * QL * DD;

    pool_kernel<<<256, 256>>>(graph, mem0);

    // split inputs + weights to bf16 hi/lo
    split_x<<<(GM * DD / 4 + 255) / 256, 256>>>(graph, xhg, xlg, GM * DD / 4);
    split_x<<<(PM * DD / 4 + 255) / 256, 256>>>(pattern, xhp, xlp, PM * DD / 4);
    split_wt<<<256, 256>>>(pW[1], wt + 0 * DD * DD, wt + 1 * DD * DD);
    split_wt<<<256, 256>>>(pW[2], wt + 2 * DD * DD, wt + 3 * DD * DD);
    split_wt<<<256, 256>>>(gW[1], wt + 4 * DD * DD, wt + 5 * DD * DD);
    split_wt<<<256, 256>>>(gW[2], wt + 6 * DD * DD, wt + 7 * DD * DD);

    // hoisted K/V projections on tensor cores (mma.sync, hi/lo 3-pass)
    gemm_mma<<<dim3(2, PM / 128), 256>>>(xhp, xlp, wt + 0 * DD * DD, wt + 1 * DD * DD, hkp);
    gemm_mma<<<dim3(2, PM / 128), 256>>>(xhp, xlp, wt + 2 * DD * DD, wt + 3 * DD * DD, hvp);
    gemm_mma<<<dim3(2, GM / 128), 256>>>(xhg, xlg, wt + 4 * DD * DD, wt + 5 * DD * DD, hkg);
    gemm_mma<<<dim3(2, GM / 128), 256>>>(xhg, xlg, wt + 6 * DD * DD, wt + 7 * DD * DD, hvg);

    float* cur = mem0;
    float* other = mem1;
    for (int it = 0; it < 3; it++) {
        for (int ph = 0; ph < 2; ph++) {
            const float* const* W = ph ? gW : pW;
            const float* hk = ph ? hkg : hkp;
            const float* hv = ph ? hvg : hvp;
            const int* mask = ph ? gmask : pmask;
            int klen = ph ? GLEN : PLEN;
            int splits = ph ? 32 : 4;
            int kps = klen / splits;

            gemm_small<<<dim3(4, 16), 256>>>(cur, W[0], hq);
            attn_partial<<<dim3(splits, NH, BB), 128>>>(hq, hk, hv, mask, klen, kps);
            attn_merge<<<dim3(NH, BB), 256>>>(vec, splits);
            gemm_small<<<dim3(4, 16), 256>>>(vec, W[3], ao);

            bool last = (it == 2 && ph == 1);
            float* dst = last ? out : other;
            gate_kernel<<<256, 256>>>(cur, ao, W[4], W[5], dst);
            other = cur;
            cur = dst;
        }
    }
}